// round 1
// baseline (speedup 1.0000x reference)
#include <cuda_runtime.h>
#include <math.h>
#include <stdint.h>

// Problem constants (fixed by the reference setup)
#define BB    2
#define NN    8192
#define DD    256
#define HH    8
#define DHD   64
#define KNB   8
#define INNER 512          // HH*DHD
#define MTOT  (BB*NN)      // 16384

// ---------------- scratch (static device globals; no allocs allowed) ----------
__device__ float g_Q  [(size_t)MTOT * INNER];       // 33.5 MB
__device__ float g_KV [(size_t)MTOT * 2 * INNER];   // 67 MB   (k | v per row)
__device__ float g_ATT[(size_t)MTOT * INNER];       // 33.5 MB
__device__ int   g_IDX[(size_t)MTOT * KNB];

// =============================================================================
// KNN kernel: one warp per query point; block of 8 warps shares candidate tiles
// in smem. Top-8 per lane via sorted insertion, then warp merge with the same
// tie-break semantics as jax.lax.top_k (lower index first on equal distance).
// =============================================================================
__global__ void __launch_bounds__(256) knn_kernel(const float* __restrict__ pos)
{
    __shared__ float s_pos[2048 * 3];   // 24KB; reused for merge staging

    const int warp  = threadIdx.x >> 5;
    const int lane  = threadIdx.x & 31;
    const int qglob = blockIdx.x * 8 + warp;          // [0, 16384)
    const int b     = qglob >> 13;                    // /8192  (block never straddles batches)
    const int qn    = qglob & (NN - 1);
    const float* posb = pos + (size_t)b * NN * 3;

    const float qx = posb[qn * 3 + 0];
    const float qy = posb[qn * 3 + 1];
    const float qz = posb[qn * 3 + 2];
    const float sqi = qx * qx + qy * qy + qz * qz;

    float bd[8];
    int   bi[8];
#pragma unroll
    for (int j = 0; j < 8; ++j) { bd[j] = __int_as_float(0x7f800000); bi[j] = 0x7fffffff; }

    for (int tile = 0; tile < NN; tile += 2048) {
        __syncthreads();
        // cooperative load of 2048 candidate positions (6144 floats = 1536 float4)
        const float4* src = (const float4*)(posb + (size_t)tile * 3);
        float4*       dst = (float4*)s_pos;
#pragma unroll
        for (int i = 0; i < 6; ++i)
            dst[threadIdx.x + 256 * i] = src[threadIdx.x + 256 * i];
        __syncthreads();

#pragma unroll 4
        for (int j = 0; j < 64; ++j) {
            const int c  = lane + 32 * j;
            const float cx = s_pos[c * 3 + 0];
            const float cy = s_pos[c * 3 + 1];
            const float cz = s_pos[c * 3 + 2];
            const float sqj = cx * cx + cy * cy + cz * cz;
            const float dot = qx * cx + qy * cy + qz * cz;
            const float d2  = (sqi + sqj) - 2.0f * dot;
            const int cid   = tile + c;
            if (d2 < bd[7]) {                      // strict <: equal keeps lower index
                bd[7] = d2; bi[7] = cid;
#pragma unroll
                for (int t = 7; t > 0; --t) {
                    if (bd[t] < bd[t - 1]) {       // strict: stable on ties
                        float tf = bd[t - 1]; bd[t - 1] = bd[t]; bd[t] = tf;
                        int   ti = bi[t - 1]; bi[t - 1] = bi[t]; bi[t] = ti;
                    }
                }
            }
        }
    }

    // ---- warp merge of 32 sorted 8-lists (reuse s_pos as staging) ----
    __syncthreads();
    float* sd = s_pos + warp * 256;                       // 8 warps * 256 floats
    int*   si = ((int*)s_pos) + 2048 + warp * 256;        // 8 warps * 256 ints
#pragma unroll
    for (int j = 0; j < 8; ++j) { sd[lane * 8 + j] = bd[j]; si[lane * 8 + j] = bi[j]; }
    __syncwarp();

    int p = 0;
    for (int r = 0; r < 8; ++r) {
        float v  = (p < 8) ? sd[lane * 8 + p] : __int_as_float(0x7f800000);
        int   ii = (p < 8) ? si[lane * 8 + p] : 0x7fffffff;
        float bv = v; int bii = ii;
#pragma unroll
        for (int o = 16; o; o >>= 1) {
            float ov = __shfl_xor_sync(0xffffffffu, bv, o);
            int   oi = __shfl_xor_sync(0xffffffffu, bii, o);
            if (ov < bv || (ov == bv && oi < bii)) { bv = ov; bii = oi; }
        }
        if (p < 8 && ii == bii) p++;      // indices are unique across lanes
        if (lane == 0) g_IDX[(size_t)qglob * 8 + r] = bii;
    }
}

// =============================================================================
// SGEMM: C[M,N] = A[M,K] * B[K,N] (+bias). 128x128x16 tiles, 256 threads,
// 8x8 micro-tile. All dims divisible by tile sizes here (no bounds checks).
// =============================================================================
__global__ void __launch_bounds__(256) sgemm_kernel(
    const float* __restrict__ A, const float* __restrict__ B,
    float* __restrict__ C, const float* __restrict__ bias,
    int M, int N, int K)
{
    __shared__ float As[16][132];   // padded to cut transpose-store conflicts
    __shared__ float Bs[16][128];

    const int tid = threadIdx.x;
    const int bx  = blockIdx.x;     // N tile
    const int by  = blockIdx.y;     // M tile
    const int tr  = tid >> 4;       // 0..15
    const int tc  = tid & 15;       // 0..15

    const float* Ablk = A + (size_t)by * 128 * K;
    const float* Bblk = B + (size_t)bx * 128;

    const int arow  = tid >> 2;          // 0..63
    const int acol4 = (tid & 3) << 2;    // 0,4,8,12
    const int brow  = tid >> 5;          // 0..7
    const int bcol4 = (tid & 31) << 2;   // 0..124

    float acc[8][8];
#pragma unroll
    for (int i = 0; i < 8; ++i)
#pragma unroll
        for (int j = 0; j < 8; ++j) acc[i][j] = 0.0f;

    for (int kt = 0; kt < K; kt += 16) {
#pragma unroll
        for (int pz = 0; pz < 2; ++pz) {
            const int r = arow + 64 * pz;
            float4 a = *(const float4*)(Ablk + (size_t)r * K + kt + acol4);
            As[acol4 + 0][r] = a.x; As[acol4 + 1][r] = a.y;
            As[acol4 + 2][r] = a.z; As[acol4 + 3][r] = a.w;
        }
#pragma unroll
        for (int pz = 0; pz < 2; ++pz) {
            const int r = brow + 8 * pz;
            *(float4*)&Bs[r][bcol4] = *(const float4*)(Bblk + (size_t)(kt + r) * N + bcol4);
        }
        __syncthreads();

#pragma unroll
        for (int k = 0; k < 16; ++k) {
            float a[8], bb[8];
            *(float4*)&a[0]  = *(const float4*)&As[k][tr * 8];
            *(float4*)&a[4]  = *(const float4*)&As[k][tr * 8 + 4];
            *(float4*)&bb[0] = *(const float4*)&Bs[k][tc * 8];
            *(float4*)&bb[4] = *(const float4*)&Bs[k][tc * 8 + 4];
#pragma unroll
            for (int i = 0; i < 8; ++i)
#pragma unroll
                for (int j = 0; j < 8; ++j)
                    acc[i][j] = fmaf(a[i], bb[j], acc[i][j]);
        }
        __syncthreads();
    }

    float bv[8];
#pragma unroll
    for (int j = 0; j < 8; ++j)
        bv[j] = bias ? bias[bx * 128 + tc * 8 + j] : 0.0f;

#pragma unroll
    for (int i = 0; i < 8; ++i) {
        const int row = by * 128 + tr * 8 + i;
        float4 o0 = make_float4(acc[i][0] + bv[0], acc[i][1] + bv[1],
                                acc[i][2] + bv[2], acc[i][3] + bv[3]);
        float4 o1 = make_float4(acc[i][4] + bv[4], acc[i][5] + bv[5],
                                acc[i][6] + bv[6], acc[i][7] + bv[7]);
        float* cp = C + (size_t)row * N + bx * 128 + tc * 8;
        *(float4*)(cp)     = o0;
        *(float4*)(cp + 4) = o1;
    }
}

// =============================================================================
// Attention: one block per point (256 thr = 8 warps = 8 heads).
// Each warp: dot q_h with 8 neighbor k_h rows (warp reduce), softmax over 8,
// weighted sum of v_h. Gather rows of KV (L2-resident) instead of materializing.
// =============================================================================
__global__ void __launch_bounds__(256) attn_kernel()
{
    const int point = blockIdx.x;            // [0, 16384)
    const int warp  = threadIdx.x >> 5;      // head
    const int lane  = threadIdx.x & 31;
    const int b     = point >> 13;
    const int baseb = b * NN;

    const int* idxp = g_IDX + (size_t)point * 8;
    const float2 qh = *(const float2*)&g_Q[(size_t)point * INNER + warp * DHD + lane * 2];

    float dots[8];
    int   nbs[8];
#pragma unroll
    for (int k = 0; k < 8; ++k) {
        const int nb = idxp[k];
        nbs[k] = nb;
        const float2 kk = *(const float2*)&g_KV[(size_t)(baseb + nb) * (2 * INNER) + warp * DHD + lane * 2];
        float d = qh.x * kk.x + qh.y * kk.y;
#pragma unroll
        for (int o = 16; o; o >>= 1) d += __shfl_xor_sync(0xffffffffu, d, o);
        dots[k] = d * 0.125f;                // DH^-0.5
    }

    float m = dots[0];
#pragma unroll
    for (int k = 1; k < 8; ++k) m = fmaxf(m, dots[k]);
    float e[8], s = 0.0f;
#pragma unroll
    for (int k = 0; k < 8; ++k) { e[k] = expf(dots[k] - m); s += e[k]; }
    const float inv = 1.0f / s;

    float2 acc = make_float2(0.0f, 0.0f);
#pragma unroll
    for (int k = 0; k < 8; ++k) {
        const float2 vv = *(const float2*)&g_KV[(size_t)(baseb + nbs[k]) * (2 * INNER) + INNER + warp * DHD + lane * 2];
        const float a = e[k] * inv;
        acc.x = fmaf(a, vv.x, acc.x);
        acc.y = fmaf(a, vv.y, acc.y);
    }
    *(float2*)&g_ATT[(size_t)point * INNER + warp * DHD + lane * 2] = acc;
}

// =============================================================================
extern "C" void kernel_launch(void* const* d_in, const int* in_sizes, int n_in,
                              void* d_out, int out_size)
{
    const float* x    = (const float*)d_in[0];
    const float* pos  = (const float*)d_in[1];
    const float* Wq   = (const float*)d_in[2];
    const float* Wkv  = (const float*)d_in[3];
    const float* Wout = (const float*)d_in[4];
    const float* bout = (const float*)d_in[5];
    float* out = (float*)d_out;

    float *pQ, *pKV, *pATT;
    cudaGetSymbolAddress((void**)&pQ,   g_Q);
    cudaGetSymbolAddress((void**)&pKV,  g_KV);
    cudaGetSymbolAddress((void**)&pATT, g_ATT);

    // 1) KNN indices
    knn_kernel<<<MTOT / 8, 256>>>(pos);

    // 2) Q = x @ Wq   [16384,256]x[256,512]
    sgemm_kernel<<<dim3(INNER / 128, MTOT / 128), 256>>>(x, Wq, pQ, nullptr,
                                                         MTOT, INNER, DD);
    // 3) KV = x @ Wkv [16384,256]x[256,1024]  (computed once, gathered later)
    sgemm_kernel<<<dim3(2 * INNER / 128, MTOT / 128), 256>>>(x, Wkv, pKV, nullptr,
                                                             MTOT, 2 * INNER, DD);
    // 4) attention over 8 gathered neighbors
    attn_kernel<<<MTOT, 256>>>();

    // 5) out = ATT @ Wout + bout  [16384,512]x[512,256]
    sgemm_kernel<<<dim3(DD / 128, MTOT / 128), 256>>>(pATT, Wout, out, bout,
                                                      MTOT, DD, INNER);
}

// round 4
// speedup vs baseline: 1.4616x; 1.4616x over previous
#include <cuda_runtime.h>
#include <cuda_bf16.h>
#include <math.h>
#include <stdint.h>

// Problem constants
#define BB    2
#define NN    8192
#define DD    256
#define HH    8
#define DHD   64
#define KNB   8
#define INNER 512
#define MTOT  (BB*NN)        // 16384
#define NQKV  (3*INNER)      // 1536 = Q | K | V

// Split-bf16 as extended-K plain GEMM:
//   A3 = [Ah | Ah | Al]  (row-major, K3 = 3K)
//   B3 = [Bh | Bl | Bh]  (N-major rows, K3 = 3K)
//   C  = Ah*Bh + Ah*Bl + Al*Bh   (fp32-accurate to ~1e-5)
#define K3_QKV (3*DD)        // 768
#define K3_OUT (3*INNER)     // 1536

// ---------------- static device scratch ----------------
__device__ __nv_bfloat16 g_X3 [(size_t)MTOT * K3_QKV];     // 25 MB
__device__ __nv_bfloat16 g_WT [(size_t)NQKV * K3_QKV];     // 2.25 MB (N-major)
__device__ __nv_bfloat16 g_WTO[(size_t)DD * K3_OUT];       // 0.75 MB (N-major)
__device__ float         g_QKV[(size_t)MTOT * NQKV];       // 100 MB
__device__ __nv_bfloat16 g_AT3[(size_t)MTOT * K3_OUT];     // 50 MB
__device__ int           g_IDX[(size_t)MTOT * KNB];

__device__ __forceinline__ uint32_t smem_u32(const void* p) {
    uint32_t a;
    asm("{ .reg .u64 t; cvta.to.shared.u64 t, %1; cvt.u32.u64 %0, t; }" : "=r"(a) : "l"(p));
    return a;
}
__device__ __forceinline__ void cp_async16(uint32_t s, const void* g) {
    asm volatile("cp.async.cg.shared.global [%0], [%1], 16;" :: "r"(s), "l"(g));
}
#define CP_COMMIT()  asm volatile("cp.async.commit_group;" ::: "memory")
#define CP_WAIT2()   asm volatile("cp.async.wait_group 2;" ::: "memory")

__device__ __forceinline__ void split_bf16(float v, __nv_bfloat16& h, __nv_bfloat16& l) {
    h = __float2bfloat16(v);
    l = __float2bfloat16(v - __bfloat162float(h));
}

// =============================================================================
// KNN (unchanged — passed round 1 with matching top_k semantics)
// =============================================================================
__global__ void __launch_bounds__(256) knn_kernel(const float* __restrict__ pos)
{
    __shared__ float s_pos[2048 * 3];

    const int warp  = threadIdx.x >> 5;
    const int lane  = threadIdx.x & 31;
    const int qglob = blockIdx.x * 8 + warp;
    const int b     = qglob >> 13;
    const int qn    = qglob & (NN - 1);
    const float* posb = pos + (size_t)b * NN * 3;

    const float qx = posb[qn * 3 + 0];
    const float qy = posb[qn * 3 + 1];
    const float qz = posb[qn * 3 + 2];
    const float sqi = qx * qx + qy * qy + qz * qz;

    float bd[8]; int bi[8];
#pragma unroll
    for (int j = 0; j < 8; ++j) { bd[j] = __int_as_float(0x7f800000); bi[j] = 0x7fffffff; }

    for (int tile = 0; tile < NN; tile += 2048) {
        __syncthreads();
        const float4* src = (const float4*)(posb + (size_t)tile * 3);
        float4*       dst = (float4*)s_pos;
#pragma unroll
        for (int i = 0; i < 6; ++i)
            dst[threadIdx.x + 256 * i] = src[threadIdx.x + 256 * i];
        __syncthreads();

#pragma unroll 4
        for (int j = 0; j < 64; ++j) {
            const int c  = lane + 32 * j;
            const float cx = s_pos[c * 3 + 0];
            const float cy = s_pos[c * 3 + 1];
            const float cz = s_pos[c * 3 + 2];
            const float sqj = cx * cx + cy * cy + cz * cz;
            const float dot = qx * cx + qy * cy + qz * cz;
            const float d2  = (sqi + sqj) - 2.0f * dot;
            const int cid   = tile + c;
            if (d2 < bd[7]) {
                bd[7] = d2; bi[7] = cid;
#pragma unroll
                for (int t = 7; t > 0; --t) {
                    if (bd[t] < bd[t - 1]) {
                        float tf = bd[t - 1]; bd[t - 1] = bd[t]; bd[t] = tf;
                        int   ti = bi[t - 1]; bi[t - 1] = bi[t]; bi[t] = ti;
                    }
                }
            }
        }
    }

    __syncthreads();
    float* sd = s_pos + warp * 256;
    int*   si = ((int*)s_pos) + 2048 + warp * 256;
#pragma unroll
    for (int j = 0; j < 8; ++j) { sd[lane * 8 + j] = bd[j]; si[lane * 8 + j] = bi[j]; }
    __syncwarp();

    int p = 0;
    for (int r = 0; r < 8; ++r) {
        float v  = (p < 8) ? sd[lane * 8 + p] : __int_as_float(0x7f800000);
        int   ii = (p < 8) ? si[lane * 8 + p] : 0x7fffffff;
        float bv = v; int bii = ii;
#pragma unroll
        for (int o = 16; o; o >>= 1) {
            float ov = __shfl_xor_sync(0xffffffffu, bv, o);
            int   oi = __shfl_xor_sync(0xffffffffu, bii, o);
            if (ov < bv || (ov == bv && oi < bii)) { bv = ov; bii = oi; }
        }
        if (p < 8 && ii == bii) p++;
        if (lane == 0) g_IDX[(size_t)qglob * 8 + r] = bii;
    }
}

// =============================================================================
// Conversions: fp32 -> split bf16, extended-K layouts.
// =============================================================================
__global__ void __launch_bounds__(256) conv_x_kernel(const float* __restrict__ x)
{
    const int idx = blockIdx.x * 256 + threadIdx.x;   // [0, MTOT*DD)
    const int row = idx >> 8, k = idx & 255;
    __nv_bfloat16 h, l;
    split_bf16(x[idx], h, l);
    __nv_bfloat16* r = g_X3 + (size_t)row * K3_QKV;
    r[k] = h; r[DD + k] = h; r[2 * DD + k] = l;       // [Ah|Ah|Al]
}

__global__ void __launch_bounds__(256) conv_wqkv_kernel(const float* __restrict__ Wq,
                                                        const float* __restrict__ Wkv)
{
    const int idx = blockIdx.x * 256 + threadIdx.x;   // [0, NQKV*DD)
    const int n = idx >> 8, k = idx & 255;
    const float v = (n < INNER) ? Wq[(size_t)k * INNER + n]
                                : Wkv[(size_t)k * (2 * INNER) + (n - INNER)];
    __nv_bfloat16 h, l; split_bf16(v, h, l);
    __nv_bfloat16* r = g_WT + (size_t)n * K3_QKV;
    r[k] = h; r[DD + k] = l; r[2 * DD + k] = h;       // [Bh|Bl|Bh]
}

__global__ void __launch_bounds__(256) conv_wout_kernel(const float* __restrict__ Wout)
{
    const int idx = blockIdx.x * 256 + threadIdx.x;   // [0, DD*INNER)
    const int n = idx >> 9, k = idx & 511;
    const float v = Wout[(size_t)k * DD + n];
    __nv_bfloat16 h, l; split_bf16(v, h, l);
    __nv_bfloat16* r = g_WTO + (size_t)n * K3_OUT;
    r[k] = h; r[INNER + k] = l; r[2 * INNER + k] = h; // [Bh|Bl|Bh]
}

// =============================================================================
// bf16 tensor-core GEMM via mma.sync. C[M,N] = A[M,K3] * Bt[N,K3]^T (+bias).
// CTA 128x128, 4 warps (2x2) of m64 x n64, K-chunk 64, 3-stage cp.async.
// smem tiles: 128 rows x 128B, chunk-XOR swizzle -> conflict-free ldmatrix.
// NOTE: B uses PLAIN ldmatrix (no .trans): Bt is N-major with K contiguous,
// so lane l already receives B[k=2(l%4)+i][n=l/4] — the .col fragment layout.
// =============================================================================
#define GSTAGES   3
#define GSTAGE_B  32768                       // A 16KB + B 16KB
#define GEMM_SMEM (GSTAGES * GSTAGE_B)        // 96 KB

__device__ __forceinline__ void mma_bf16(float* d, const uint32_t* a, const uint32_t* b)
{
    asm volatile(
        "mma.sync.aligned.m16n8k16.row.col.f32.bf16.bf16.f32 "
        "{%0,%1,%2,%3}, {%4,%5,%6,%7}, {%8,%9}, {%0,%1,%2,%3};"
        : "+f"(d[0]), "+f"(d[1]), "+f"(d[2]), "+f"(d[3])
        : "r"(a[0]), "r"(a[1]), "r"(a[2]), "r"(a[3]), "r"(b[0]), "r"(b[1]));
}

__global__ void __launch_bounds__(128) gemm_mma_kernel(
    const __nv_bfloat16* __restrict__ A,   // [M, K3] row-major
    const __nv_bfloat16* __restrict__ Bt,  // [N, K3] row-major (N-major weights)
    float* __restrict__ C, const float* __restrict__ bias,
    int Nglob, int K3)
{
    extern __shared__ char smem[];
    const uint32_t sb = smem_u32(smem);
    const int tid  = threadIdx.x;
    const int warp = tid >> 5, lane = tid & 31;
    const int wm = warp & 1, wn = warp >> 1;
    const int m0 = blockIdx.y * 128, n0 = blockIdx.x * 128;
    const int nch = K3 >> 6;

    float acc[4][8][4];
#pragma unroll
    for (int i = 0; i < 4; ++i)
#pragma unroll
        for (int j = 0; j < 8; ++j)
#pragma unroll
            for (int t = 0; t < 4; ++t) acc[i][j][t] = 0.0f;

    auto load_stage = [&](int s, int kc) {
        const uint32_t st = sb + s * GSTAGE_B;
#pragma unroll
        for (int it = 0; it < 8; ++it) {
            const int idx = it * 128 + tid;
            const int row = idx >> 3, c = idx & 7;
            cp_async16(st + row * 128 + ((c ^ (row & 7)) << 4),
                       A + (size_t)(m0 + row) * K3 + kc * 64 + c * 8);
        }
#pragma unroll
        for (int it = 0; it < 8; ++it) {
            const int idx = it * 128 + tid;
            const int row = idx >> 3, c = idx & 7;
            cp_async16(st + 16384 + row * 128 + ((c ^ (row & 7)) << 4),
                       Bt + (size_t)(n0 + row) * K3 + kc * 64 + c * 8);
        }
    };

    load_stage(0, 0); CP_COMMIT();
    load_stage(1, 1); CP_COMMIT();

    for (int i = 0; i < nch; ++i) {
        if (i + 2 < nch) load_stage((i + 2) % GSTAGES, i + 2);
        CP_COMMIT();
        CP_WAIT2();
        __syncthreads();

        const uint32_t stA = sb + (i % GSTAGES) * GSTAGE_B;
        const uint32_t stB = stA + 16384;

#pragma unroll
        for (int ks = 0; ks < 4; ++ks) {
            uint32_t af[4][4];
#pragma unroll
            for (int mi = 0; mi < 4; ++mi) {
                const int row = wm * 64 + mi * 16 + (lane & 15);
                const int kc  = 2 * ks + (lane >> 4);
                const uint32_t a = stA + row * 128 + ((kc ^ (row & 7)) << 4);
                asm volatile("ldmatrix.sync.aligned.m8n8.x4.shared.b16 {%0,%1,%2,%3}, [%4];"
                    : "=r"(af[mi][0]), "=r"(af[mi][1]), "=r"(af[mi][2]), "=r"(af[mi][3])
                    : "r"(a));
            }
            uint32_t bf[4][4];
#pragma unroll
            for (int nj = 0; nj < 4; ++nj) {
                const int row = wn * 64 + nj * 16 + ((lane & 16) >> 1) + (lane & 7);
                const int kc  = 2 * ks + ((lane >> 3) & 1);
                const uint32_t a = stB + row * 128 + ((kc ^ (row & 7)) << 4);
                asm volatile("ldmatrix.sync.aligned.m8n8.x4.shared.b16 {%0,%1,%2,%3}, [%4];"
                    : "=r"(bf[nj][0]), "=r"(bf[nj][1]), "=r"(bf[nj][2]), "=r"(bf[nj][3])
                    : "r"(a));
            }
#pragma unroll
            for (int mi = 0; mi < 4; ++mi)
#pragma unroll
                for (int nj = 0; nj < 8; ++nj)
                    mma_bf16(acc[mi][nj], af[mi], &bf[nj >> 1][(nj & 1) * 2]);
        }
        __syncthreads();
    }

    // epilogue
    const int g = lane >> 2, tg = lane & 3;
#pragma unroll
    for (int mi = 0; mi < 4; ++mi) {
        const int r0 = m0 + wm * 64 + mi * 16 + g;
#pragma unroll
        for (int nj = 0; nj < 8; ++nj) {
            const int col = n0 + wn * 64 + nj * 8 + tg * 2;
            float b0 = 0.0f, b1 = 0.0f;
            if (bias) { b0 = bias[col]; b1 = bias[col + 1]; }
            float2 o0 = make_float2(acc[mi][nj][0] + b0, acc[mi][nj][1] + b1);
            float2 o1 = make_float2(acc[mi][nj][2] + b0, acc[mi][nj][3] + b1);
            *(float2*)&C[(size_t)r0 * Nglob + col]       = o0;
            *(float2*)&C[(size_t)(r0 + 8) * Nglob + col] = o1;
        }
    }
}

// =============================================================================
// Attention: one block per point (8 warps = 8 heads); reads fused QKV,
// writes split-bf16 activation in extended-K layout [h|h|l].
// =============================================================================
__global__ void __launch_bounds__(256) attn_kernel()
{
    const int point = blockIdx.x;
    const int warp  = threadIdx.x >> 5;
    const int lane  = threadIdx.x & 31;
    const int b     = point >> 13;
    const int baseb = b * NN;

    const int* idxp = g_IDX + (size_t)point * 8;
    const float2 qh = *(const float2*)&g_QKV[(size_t)point * NQKV + warp * DHD + lane * 2];

    float dots[8];
    int   nbs[8];
#pragma unroll
    for (int k = 0; k < 8; ++k) {
        const int nb = idxp[k];
        nbs[k] = nb;
        const float2 kk = *(const float2*)&g_QKV[(size_t)(baseb + nb) * NQKV + INNER + warp * DHD + lane * 2];
        float d = qh.x * kk.x + qh.y * kk.y;
#pragma unroll
        for (int o = 16; o; o >>= 1) d += __shfl_xor_sync(0xffffffffu, d, o);
        dots[k] = d * 0.125f;
    }

    float m = dots[0];
#pragma unroll
    for (int k = 1; k < 8; ++k) m = fmaxf(m, dots[k]);
    float e[8], s = 0.0f;
#pragma unroll
    for (int k = 0; k < 8; ++k) { e[k] = expf(dots[k] - m); s += e[k]; }
    const float inv = 1.0f / s;

    float2 acc = make_float2(0.0f, 0.0f);
#pragma unroll
    for (int k = 0; k < 8; ++k) {
        const float2 vv = *(const float2*)&g_QKV[(size_t)(baseb + nbs[k]) * NQKV + 2 * INNER + warp * DHD + lane * 2];
        const float a = e[k] * inv;
        acc.x = fmaf(a, vv.x, acc.x);
        acc.y = fmaf(a, vv.y, acc.y);
    }

    __nv_bfloat16 hx, lx, hy, ly;
    split_bf16(acc.x, hx, lx);
    split_bf16(acc.y, hy, ly);
    __nv_bfloat162 hp; hp.x = hx; hp.y = hy;
    __nv_bfloat162 lp; lp.x = lx; lp.y = ly;
    __nv_bfloat16* r = g_AT3 + (size_t)point * K3_OUT + warp * DHD + lane * 2;
    *(__nv_bfloat162*)(r)             = hp;   // Ah
    *(__nv_bfloat162*)(r + INNER)     = hp;   // Ah
    *(__nv_bfloat162*)(r + 2 * INNER) = lp;   // Al
}

// =============================================================================
extern "C" void kernel_launch(void* const* d_in, const int* in_sizes, int n_in,
                              void* d_out, int out_size)
{
    const float* x    = (const float*)d_in[0];
    const float* pos  = (const float*)d_in[1];
    const float* Wq   = (const float*)d_in[2];
    const float* Wkv  = (const float*)d_in[3];
    const float* Wout = (const float*)d_in[4];
    const float* bout = (const float*)d_in[5];
    float* out = (float*)d_out;

    cudaFuncSetAttribute(gemm_mma_kernel,
                         cudaFuncAttributeMaxDynamicSharedMemorySize, GEMM_SMEM);

    __nv_bfloat16 *pX3, *pWT, *pWTO, *pAT3;
    float *pQKV;
    cudaGetSymbolAddress((void**)&pX3,  g_X3);
    cudaGetSymbolAddress((void**)&pWT,  g_WT);
    cudaGetSymbolAddress((void**)&pWTO, g_WTO);
    cudaGetSymbolAddress((void**)&pQKV, g_QKV);
    cudaGetSymbolAddress((void**)&pAT3, g_AT3);

    // 1) KNN + conversions
    knn_kernel<<<MTOT / 8, 256>>>(pos);
    conv_x_kernel<<<MTOT * DD / 256, 256>>>(x);
    conv_wqkv_kernel<<<NQKV * DD / 256, 256>>>(Wq, Wkv);
    conv_wout_kernel<<<DD * INNER / 256, 256>>>(Wout);

    // 2) fused QKV = x @ [Wq|Wkv]  (tensor cores, split-bf16 as K'=768)
    gemm_mma_kernel<<<dim3(NQKV / 128, MTOT / 128), 128, GEMM_SMEM>>>(
        pX3, pWT, pQKV, nullptr, NQKV, K3_QKV);

    // 3) neighbor attention (writes extended-K split-bf16 activation)
    attn_kernel<<<MTOT, 256>>>();

    // 4) out = ATT @ Wout + bout   (tensor cores, split-bf16 as K'=1536)
    gemm_mma_kernel<<<dim3(DD / 128, MTOT / 128), 128, GEMM_SMEM>>>(
        pAT3, pWTO, out, bout, DD, K3_OUT);
}

// round 5
// speedup vs baseline: 1.5002x; 1.0264x over previous
#include <cuda_runtime.h>
#include <cuda_bf16.h>
#include <math.h>
#include <stdint.h>

// Problem constants
#define BB    2
#define NN    8192
#define DD    256
#define HH    8
#define DHD   64
#define KNB   8
#define INNER 512
#define MTOT  (BB*NN)        // 16384
#define NQKV  (3*INNER)      // 1536 = Q | K | V

// Split-bf16 as extended-K plain GEMM:
//   A3 = [Ah | Ah | Al]  (row-major, K3 = 3K)
//   B3 = [Bh | Bl | Bh]  (N-major rows, K3 = 3K)
//   C  = Ah*Bh + Ah*Bl + Al*Bh   (fp32-accurate to ~1e-5)
#define K3_QKV (3*DD)        // 768
#define K3_OUT (3*INNER)     // 1536

// ---------------- static device scratch ----------------
__device__ __nv_bfloat16 g_X3 [(size_t)MTOT * K3_QKV];     // 25 MB
__device__ __nv_bfloat16 g_WT [(size_t)NQKV * K3_QKV];     // 2.25 MB (N-major)
__device__ __nv_bfloat16 g_WTO[(size_t)DD * K3_OUT];       // 0.75 MB (N-major)
__device__ float         g_QKV[(size_t)MTOT * NQKV];       // 100 MB
__device__ __nv_bfloat16 g_AT3[(size_t)MTOT * K3_OUT];     // 50 MB
__device__ int           g_IDX[(size_t)MTOT * KNB];

__device__ __forceinline__ uint32_t smem_u32(const void* p) {
    uint32_t a;
    asm("{ .reg .u64 t; cvta.to.shared.u64 t, %1; cvt.u32.u64 %0, t; }" : "=r"(a) : "l"(p));
    return a;
}
__device__ __forceinline__ void cp_async16(uint32_t s, const void* g) {
    asm volatile("cp.async.cg.shared.global [%0], [%1], 16;" :: "r"(s), "l"(g));
}
#define CP_COMMIT()  asm volatile("cp.async.commit_group;" ::: "memory")
#define CP_WAIT2()   asm volatile("cp.async.wait_group 2;" ::: "memory")

__device__ __forceinline__ void split_bf16(float v, __nv_bfloat16& h, __nv_bfloat16& l) {
    h = __float2bfloat16(v);
    l = __float2bfloat16(v - __bfloat162float(h));
}

// =============================================================================
// KNN (unchanged — passes with matching top_k semantics)
// =============================================================================
__global__ void __launch_bounds__(256) knn_kernel(const float* __restrict__ pos)
{
    __shared__ float s_pos[2048 * 3];

    const int warp  = threadIdx.x >> 5;
    const int lane  = threadIdx.x & 31;
    const int qglob = blockIdx.x * 8 + warp;
    const int b     = qglob >> 13;
    const int qn    = qglob & (NN - 1);
    const float* posb = pos + (size_t)b * NN * 3;

    const float qx = posb[qn * 3 + 0];
    const float qy = posb[qn * 3 + 1];
    const float qz = posb[qn * 3 + 2];
    const float sqi = qx * qx + qy * qy + qz * qz;

    float bd[8]; int bi[8];
#pragma unroll
    for (int j = 0; j < 8; ++j) { bd[j] = __int_as_float(0x7f800000); bi[j] = 0x7fffffff; }

    for (int tile = 0; tile < NN; tile += 2048) {
        __syncthreads();
        const float4* src = (const float4*)(posb + (size_t)tile * 3);
        float4*       dst = (float4*)s_pos;
#pragma unroll
        for (int i = 0; i < 6; ++i)
            dst[threadIdx.x + 256 * i] = src[threadIdx.x + 256 * i];
        __syncthreads();

#pragma unroll 4
        for (int j = 0; j < 64; ++j) {
            const int c  = lane + 32 * j;
            const float cx = s_pos[c * 3 + 0];
            const float cy = s_pos[c * 3 + 1];
            const float cz = s_pos[c * 3 + 2];
            const float sqj = cx * cx + cy * cy + cz * cz;
            const float dot = qx * cx + qy * cy + qz * cz;
            const float d2  = (sqi + sqj) - 2.0f * dot;
            const int cid   = tile + c;
            if (d2 < bd[7]) {
                bd[7] = d2; bi[7] = cid;
#pragma unroll
                for (int t = 7; t > 0; --t) {
                    if (bd[t] < bd[t - 1]) {
                        float tf = bd[t - 1]; bd[t - 1] = bd[t]; bd[t] = tf;
                        int   ti = bi[t - 1]; bi[t - 1] = bi[t]; bi[t] = ti;
                    }
                }
            }
        }
    }

    __syncthreads();
    float* sd = s_pos + warp * 256;
    int*   si = ((int*)s_pos) + 2048 + warp * 256;
#pragma unroll
    for (int j = 0; j < 8; ++j) { sd[lane * 8 + j] = bd[j]; si[lane * 8 + j] = bi[j]; }
    __syncwarp();

    int p = 0;
    for (int r = 0; r < 8; ++r) {
        float v  = (p < 8) ? sd[lane * 8 + p] : __int_as_float(0x7f800000);
        int   ii = (p < 8) ? si[lane * 8 + p] : 0x7fffffff;
        float bv = v; int bii = ii;
#pragma unroll
        for (int o = 16; o; o >>= 1) {
            float ov = __shfl_xor_sync(0xffffffffu, bv, o);
            int   oi = __shfl_xor_sync(0xffffffffu, bii, o);
            if (ov < bv || (ov == bv && oi < bii)) { bv = ov; bii = oi; }
        }
        if (p < 8 && ii == bii) p++;
        if (lane == 0) g_IDX[(size_t)qglob * 8 + r] = bii;
    }
}

// =============================================================================
// Conversions: fp32 -> split bf16, extended-K layouts.
// =============================================================================
__global__ void __launch_bounds__(256) conv_x_kernel(const float* __restrict__ x)
{
    const int idx = blockIdx.x * 256 + threadIdx.x;   // [0, MTOT*DD)
    const int row = idx >> 8, k = idx & 255;
    __nv_bfloat16 h, l;
    split_bf16(x[idx], h, l);
    __nv_bfloat16* r = g_X3 + (size_t)row * K3_QKV;
    r[k] = h; r[DD + k] = h; r[2 * DD + k] = l;       // [Ah|Ah|Al]
}

__global__ void __launch_bounds__(256) conv_wqkv_kernel(const float* __restrict__ Wq,
                                                        const float* __restrict__ Wkv)
{
    const int idx = blockIdx.x * 256 + threadIdx.x;   // [0, NQKV*DD)
    const int n = idx >> 8, k = idx & 255;
    const float v = (n < INNER) ? Wq[(size_t)k * INNER + n]
                                : Wkv[(size_t)k * (2 * INNER) + (n - INNER)];
    __nv_bfloat16 h, l; split_bf16(v, h, l);
    __nv_bfloat16* r = g_WT + (size_t)n * K3_QKV;
    r[k] = h; r[DD + k] = l; r[2 * DD + k] = h;       // [Bh|Bl|Bh]
}

__global__ void __launch_bounds__(256) conv_wout_kernel(const float* __restrict__ Wout)
{
    const int idx = blockIdx.x * 256 + threadIdx.x;   // [0, DD*INNER)
    const int n = idx >> 9, k = idx & 511;
    const float v = Wout[(size_t)k * DD + n];
    __nv_bfloat16 h, l; split_bf16(v, h, l);
    __nv_bfloat16* r = g_WTO + (size_t)n * K3_OUT;
    r[k] = h; r[INNER + k] = l; r[2 * INNER + k] = h; // [Bh|Bl|Bh]
}

// =============================================================================
// bf16 tensor-core GEMM via mma.sync. C[M,N] = A[M,K3] * Bt[N,K3]^T (+bias).
// CTA 128x128, 4 warps (2x2) of m64 x n64, K-chunk 64, 3-stage cp.async,
// register-fragment DOUBLE BUFFERING: LDSM for ks+1 issued before MMAs of ks
// so the ~30cyc ldmatrix latency is hidden under 32 HMMAs.
// B uses PLAIN ldmatrix (no .trans): Bt is N-major with K contiguous.
// =============================================================================
#define GSTAGES   3
#define GSTAGE_B  32768                       // A 16KB + B 16KB
#define GEMM_SMEM (GSTAGES * GSTAGE_B)        // 96 KB

__device__ __forceinline__ void mma_bf16(float* d, const uint32_t* a, const uint32_t* b)
{
    asm volatile(
        "mma.sync.aligned.m16n8k16.row.col.f32.bf16.bf16.f32 "
        "{%0,%1,%2,%3}, {%4,%5,%6,%7}, {%8,%9}, {%0,%1,%2,%3};"
        : "+f"(d[0]), "+f"(d[1]), "+f"(d[2]), "+f"(d[3])
        : "r"(a[0]), "r"(a[1]), "r"(a[2]), "r"(a[3]), "r"(b[0]), "r"(b[1]));
}

__device__ __forceinline__ void ldsm_x4(uint32_t* r, uint32_t a)
{
    asm volatile("ldmatrix.sync.aligned.m8n8.x4.shared.b16 {%0,%1,%2,%3}, [%4];"
        : "=r"(r[0]), "=r"(r[1]), "=r"(r[2]), "=r"(r[3]) : "r"(a));
}

__global__ void __launch_bounds__(128) gemm_mma_kernel(
    const __nv_bfloat16* __restrict__ A,   // [M, K3] row-major
    const __nv_bfloat16* __restrict__ Bt,  // [N, K3] row-major (N-major weights)
    float* __restrict__ C, const float* __restrict__ bias,
    int Nglob, int K3)
{
    extern __shared__ char smem[];
    const uint32_t sb = smem_u32(smem);
    const int tid  = threadIdx.x;
    const int warp = tid >> 5, lane = tid & 31;
    const int wm = warp & 1, wn = warp >> 1;
    const int m0 = blockIdx.y * 128, n0 = blockIdx.x * 128;
    const int nch = K3 >> 6;

    float acc[4][8][4];
#pragma unroll
    for (int i = 0; i < 4; ++i)
#pragma unroll
        for (int j = 0; j < 8; ++j)
#pragma unroll
            for (int t = 0; t < 4; ++t) acc[i][j][t] = 0.0f;

    // precomputed per-thread ldmatrix row/kc components
    const int a_row = wm * 64 + (lane & 15);          // + mi*16
    const int a_k   = (lane >> 4);                    // + 2*ks
    const int b_row = wn * 64 + ((lane & 16) >> 1) + (lane & 7);   // + nj*16
    const int b_k   = ((lane >> 3) & 1);              // + 2*ks

    auto load_stage = [&](int s, int kc) {
        const uint32_t st = sb + s * GSTAGE_B;
#pragma unroll
        for (int it = 0; it < 8; ++it) {
            const int idx = it * 128 + tid;
            const int row = idx >> 3, c = idx & 7;
            cp_async16(st + row * 128 + ((c ^ (row & 7)) << 4),
                       A + (size_t)(m0 + row) * K3 + kc * 64 + c * 8);
        }
#pragma unroll
        for (int it = 0; it < 8; ++it) {
            const int idx = it * 128 + tid;
            const int row = idx >> 3, c = idx & 7;
            cp_async16(st + 16384 + row * 128 + ((c ^ (row & 7)) << 4),
                       Bt + (size_t)(n0 + row) * K3 + kc * 64 + c * 8);
        }
    };

    load_stage(0, 0); CP_COMMIT();
    load_stage(1, 1); CP_COMMIT();

    uint32_t af[2][4][4], bf[2][4][4];

    for (int i = 0; i < nch; ++i) {
        if (i + 2 < nch) load_stage((i + 2) % GSTAGES, i + 2);
        CP_COMMIT();
        CP_WAIT2();
        __syncthreads();

        const uint32_t stA = sb + (i % GSTAGES) * GSTAGE_B;
        const uint32_t stB = stA + 16384;

        // frag loader for a given ks into buffer slot
        auto load_frags = [&](int ks, int slot) {
#pragma unroll
            for (int mi = 0; mi < 4; ++mi) {
                const int row = a_row + mi * 16;
                const int kc  = 2 * ks + a_k;
                ldsm_x4(af[slot][mi], stA + row * 128 + ((kc ^ (row & 7)) << 4));
            }
#pragma unroll
            for (int nj = 0; nj < 4; ++nj) {
                const int row = b_row + nj * 16;
                const int kc  = 2 * ks + b_k;
                ldsm_x4(bf[slot][nj], stB + row * 128 + ((kc ^ (row & 7)) << 4));
            }
        };

        load_frags(0, 0);
#pragma unroll
        for (int ks = 0; ks < 4; ++ks) {
            const int cur = ks & 1;
            if (ks < 3) load_frags(ks + 1, cur ^ 1);   // prefetch next frags
#pragma unroll
            for (int mi = 0; mi < 4; ++mi)
#pragma unroll
                for (int nj = 0; nj < 8; ++nj)
                    mma_bf16(acc[mi][nj], af[cur][mi], &bf[cur][nj >> 1][(nj & 1) * 2]);
        }
        __syncthreads();
    }

    // epilogue
    const int g = lane >> 2, tg = lane & 3;
#pragma unroll
    for (int mi = 0; mi < 4; ++mi) {
        const int r0 = m0 + wm * 64 + mi * 16 + g;
#pragma unroll
        for (int nj = 0; nj < 8; ++nj) {
            const int col = n0 + wn * 64 + nj * 8 + tg * 2;
            float b0 = 0.0f, b1 = 0.0f;
            if (bias) { b0 = bias[col]; b1 = bias[col + 1]; }
            float2 o0 = make_float2(acc[mi][nj][0] + b0, acc[mi][nj][1] + b1);
            float2 o1 = make_float2(acc[mi][nj][2] + b0, acc[mi][nj][3] + b1);
            *(float2*)&C[(size_t)r0 * Nglob + col]       = o0;
            *(float2*)&C[(size_t)(r0 + 8) * Nglob + col] = o1;
        }
    }
}

// =============================================================================
// Attention: one block per point (8 warps = 8 heads); reads fused QKV,
// writes split-bf16 activation in extended-K layout [h|h|l].
// =============================================================================
__global__ void __launch_bounds__(256) attn_kernel()
{
    const int point = blockIdx.x;
    const int warp  = threadIdx.x >> 5;
    const int lane  = threadIdx.x & 31;
    const int b     = point >> 13;
    const int baseb = b * NN;

    const int* idxp = g_IDX + (size_t)point * 8;
    const float2 qh = *(const float2*)&g_QKV[(size_t)point * NQKV + warp * DHD + lane * 2];

    float dots[8];
    int   nbs[8];
#pragma unroll
    for (int k = 0; k < 8; ++k) {
        const int nb = idxp[k];
        nbs[k] = nb;
        const float2 kk = *(const float2*)&g_QKV[(size_t)(baseb + nb) * NQKV + INNER + warp * DHD + lane * 2];
        float d = qh.x * kk.x + qh.y * kk.y;
#pragma unroll
        for (int o = 16; o; o >>= 1) d += __shfl_xor_sync(0xffffffffu, d, o);
        dots[k] = d * 0.125f;
    }

    float m = dots[0];
#pragma unroll
    for (int k = 1; k < 8; ++k) m = fmaxf(m, dots[k]);
    float e[8], s = 0.0f;
#pragma unroll
    for (int k = 0; k < 8; ++k) { e[k] = expf(dots[k] - m); s += e[k]; }
    const float inv = 1.0f / s;

    float2 acc = make_float2(0.0f, 0.0f);
#pragma unroll
    for (int k = 0; k < 8; ++k) {
        const float2 vv = *(const float2*)&g_QKV[(size_t)(baseb + nbs[k]) * NQKV + 2 * INNER + warp * DHD + lane * 2];
        const float a = e[k] * inv;
        acc.x = fmaf(a, vv.x, acc.x);
        acc.y = fmaf(a, vv.y, acc.y);
    }

    __nv_bfloat16 hx, lx, hy, ly;
    split_bf16(acc.x, hx, lx);
    split_bf16(acc.y, hy, ly);
    __nv_bfloat162 hp; hp.x = hx; hp.y = hy;
    __nv_bfloat162 lp; lp.x = lx; lp.y = ly;
    __nv_bfloat16* r = g_AT3 + (size_t)point * K3_OUT + warp * DHD + lane * 2;
    *(__nv_bfloat162*)(r)             = hp;   // Ah
    *(__nv_bfloat162*)(r + INNER)     = hp;   // Ah
    *(__nv_bfloat162*)(r + 2 * INNER) = lp;   // Al
}

// =============================================================================
extern "C" void kernel_launch(void* const* d_in, const int* in_sizes, int n_in,
                              void* d_out, int out_size)
{
    const float* x    = (const float*)d_in[0];
    const float* pos  = (const float*)d_in[1];
    const float* Wq   = (const float*)d_in[2];
    const float* Wkv  = (const float*)d_in[3];
    const float* Wout = (const float*)d_in[4];
    const float* bout = (const float*)d_in[5];
    float* out = (float*)d_out;

    cudaFuncSetAttribute(gemm_mma_kernel,
                         cudaFuncAttributeMaxDynamicSharedMemorySize, GEMM_SMEM);

    __nv_bfloat16 *pX3, *pWT, *pWTO, *pAT3;
    float *pQKV;
    cudaGetSymbolAddress((void**)&pX3,  g_X3);
    cudaGetSymbolAddress((void**)&pWT,  g_WT);
    cudaGetSymbolAddress((void**)&pWTO, g_WTO);
    cudaGetSymbolAddress((void**)&pQKV, g_QKV);
    cudaGetSymbolAddress((void**)&pAT3, g_AT3);

    // 1) KNN + conversions
    knn_kernel<<<MTOT / 8, 256>>>(pos);
    conv_x_kernel<<<MTOT * DD / 256, 256>>>(x);
    conv_wqkv_kernel<<<NQKV * DD / 256, 256>>>(Wq, Wkv);
    conv_wout_kernel<<<DD * INNER / 256, 256>>>(Wout);

    // 2) fused QKV = x @ [Wq|Wkv]  (tensor cores, split-bf16 as K'=768)
    gemm_mma_kernel<<<dim3(NQKV / 128, MTOT / 128), 128, GEMM_SMEM>>>(
        pX3, pWT, pQKV, nullptr, NQKV, K3_QKV);

    // 3) neighbor attention (writes extended-K split-bf16 activation)
    attn_kernel<<<MTOT, 256>>>();

    // 4) out = ATT @ Wout + bout   (tensor cores, split-bf16 as K'=1536)
    gemm_mma_kernel<<<dim3(DD / 128, MTOT / 128), 128, GEMM_SMEM>>>(
        pAT3, pWTO, out, bout, DD, K3_OUT);
}

// round 6
// speedup vs baseline: 1.6271x; 1.0846x over previous
#include <cuda_runtime.h>
#include <cuda_fp16.h>
#include <math.h>
#include <stdint.h>

// Problem constants
#define BB    2
#define NN    8192
#define DD    256
#define HH    8
#define DHD   64
#define KNB   8
#define INNER 512
#define MTOT  (BB*NN)        // 16384
#define NQKV  (3*INNER)      // 1536 = Q | K | V

// 2-term fp16 split as extended-K plain GEMM:
//   A2 = [Ah | Al]  (row-major, K2 = 2K), Ah = fp16(a), Al = fp16(a - Ah)
//   B2 = [Bh | Bh]  (N-major rows, hi duplicated)
//   C  = (Ah + Al)·Bh = A·Bh  -> only error is fp16 rounding of B (~1e-4 rms)
#define K2_QKV (2*DD)        // 512
#define K2_OUT (2*INNER)     // 1024

// ---------------- static device scratch ----------------
__device__ __half g_X2 [(size_t)MTOT * K2_QKV];     // 16.8 MB
__device__ __half g_WT [(size_t)NQKV * K2_QKV];     // 1.5 MB (N-major)
__device__ __half g_WTO[(size_t)DD * K2_OUT];       // 0.5 MB (N-major)
__device__ float  g_QKV[(size_t)MTOT * NQKV];       // 100 MB
__device__ __half g_AT2[(size_t)MTOT * K2_OUT];     // 33.6 MB
__device__ int    g_IDX[(size_t)MTOT * KNB];

__device__ __forceinline__ uint32_t smem_u32(const void* p) {
    uint32_t a;
    asm("{ .reg .u64 t; cvta.to.shared.u64 t, %1; cvt.u32.u64 %0, t; }" : "=r"(a) : "l"(p));
    return a;
}
__device__ __forceinline__ void cp_async16(uint32_t s, const void* g) {
    asm volatile("cp.async.cg.shared.global [%0], [%1], 16;" :: "r"(s), "l"(g));
}
#define CP_COMMIT()  asm volatile("cp.async.commit_group;" ::: "memory")
#define CP_WAIT2()   asm volatile("cp.async.wait_group 2;" ::: "memory")

__device__ __forceinline__ void split_f16(float v, __half& h, __half& l) {
    h = __float2half(v);
    l = __float2half(v - __half2float(h));
}

// =============================================================================
// KNN: one warp per query; candidates staged as float4 (x,y,z,|c|^2) in smem;
// |q|^2 folded out of the comparison (constant shift preserves ordering+ties).
// Per candidate: 1 LDS.128 + 3 FMA + cmp.
// =============================================================================
__global__ void __launch_bounds__(256) knn_kernel(const float* __restrict__ pos)
{
    __shared__ float4 s_c4[1024];        // 16KB; reused as merge staging
    __shared__ float  s_raw[1024 * 3];   // 12KB

    const int tid   = threadIdx.x;
    const int warp  = tid >> 5;
    const int lane  = tid & 31;
    const int qglob = blockIdx.x * 8 + warp;
    const int b     = qglob >> 13;
    const int qn    = qglob & (NN - 1);
    const float* posb = pos + (size_t)b * NN * 3;

    const float qx2 = -2.0f * posb[qn * 3 + 0];
    const float qy2 = -2.0f * posb[qn * 3 + 1];
    const float qz2 = -2.0f * posb[qn * 3 + 2];

    float bd[8]; int bi[8];
#pragma unroll
    for (int j = 0; j < 8; ++j) { bd[j] = __int_as_float(0x7f800000); bi[j] = 0x7fffffff; }

    for (int tile = 0; tile < NN; tile += 1024) {
        __syncthreads();
        // bulk load 1024 positions (3072 floats = 768 float4)
        const float4* src = (const float4*)(posb + (size_t)tile * 3);
        float4*       dst = (float4*)s_raw;
#pragma unroll
        for (int i = 0; i < 3; ++i)
            dst[tid + 256 * i] = src[tid + 256 * i];
        __syncthreads();
        // convert to (x,y,z,|c|^2)
#pragma unroll
        for (int i = 0; i < 4; ++i) {
            const int c = tid + 256 * i;
            const float cx = s_raw[c * 3 + 0];
            const float cy = s_raw[c * 3 + 1];
            const float cz = s_raw[c * 3 + 2];
            s_c4[c] = make_float4(cx, cy, cz, cx * cx + cy * cy + cz * cz);
        }
        __syncthreads();

#pragma unroll 4
        for (int j = 0; j < 32; ++j) {
            const int c = lane + 32 * j;
            const float4 p = s_c4[c];
            // d2 - |q|^2 = |c|^2 - 2 q.c   (same ordering as d2)
            const float t = fmaf(p.x, qx2, fmaf(p.y, qy2, fmaf(p.z, qz2, p.w)));
            const int cid = tile + c;
            if (t < bd[7]) {                       // strict <: equal keeps lower index
                bd[7] = t; bi[7] = cid;
#pragma unroll
                for (int u = 7; u > 0; --u) {
                    if (bd[u] < bd[u - 1]) {
                        float tf = bd[u - 1]; bd[u - 1] = bd[u]; bd[u] = tf;
                        int   ti = bi[u - 1]; bi[u - 1] = bi[u]; bi[u] = ti;
                    }
                }
            }
        }
    }

    // ---- warp merge of 32 sorted 8-lists (staging in s_c4 region: 16KB) ----
    __syncthreads();
    float* sd = (float*)s_c4 + warp * 256;            // 8 warps * 256 floats = 8KB
    int*   si = ((int*)s_c4) + 2048 + warp * 256;     // next 8KB
#pragma unroll
    for (int j = 0; j < 8; ++j) { sd[lane * 8 + j] = bd[j]; si[lane * 8 + j] = bi[j]; }
    __syncwarp();

    int p = 0;
    for (int r = 0; r < 8; ++r) {
        float v  = (p < 8) ? sd[lane * 8 + p] : __int_as_float(0x7f800000);
        int   ii = (p < 8) ? si[lane * 8 + p] : 0x7fffffff;
        float bv = v; int bii = ii;
#pragma unroll
        for (int o = 16; o; o >>= 1) {
            float ov = __shfl_xor_sync(0xffffffffu, bv, o);
            int   oi = __shfl_xor_sync(0xffffffffu, bii, o);
            if (ov < bv || (ov == bv && oi < bii)) { bv = ov; bii = oi; }
        }
        if (p < 8 && ii == bii) p++;
        if (lane == 0) g_IDX[(size_t)qglob * 8 + r] = bii;
    }
}

// =============================================================================
// Conversions: fp32 -> fp16 (A: hi|lo split, B: hi duplicated), extended-K.
// =============================================================================
__global__ void __launch_bounds__(256) conv_x_kernel(const float* __restrict__ x)
{
    const int idx = blockIdx.x * 256 + threadIdx.x;   // [0, MTOT*DD)
    const int row = idx >> 8, k = idx & 255;
    __half h, l;
    split_f16(x[idx], h, l);
    __half* r = g_X2 + (size_t)row * K2_QKV;
    r[k] = h; r[DD + k] = l;                          // [Ah|Al]
}

__global__ void __launch_bounds__(256) conv_wqkv_kernel(const float* __restrict__ Wq,
                                                        const float* __restrict__ Wkv)
{
    const int idx = blockIdx.x * 256 + threadIdx.x;   // [0, NQKV*DD)
    const int n = idx >> 8, k = idx & 255;
    const float v = (n < INNER) ? Wq[(size_t)k * INNER + n]
                                : Wkv[(size_t)k * (2 * INNER) + (n - INNER)];
    const __half h = __float2half(v);
    __half* r = g_WT + (size_t)n * K2_QKV;
    r[k] = h; r[DD + k] = h;                          // [Bh|Bh]
}

__global__ void __launch_bounds__(256) conv_wout_kernel(const float* __restrict__ Wout)
{
    const int idx = blockIdx.x * 256 + threadIdx.x;   // [0, DD*INNER)
    const int n = idx >> 9, k = idx & 511;
    const __half h = __float2half(Wout[(size_t)k * DD + n]);
    __half* r = g_WTO + (size_t)n * K2_OUT;
    r[k] = h; r[INNER + k] = h;                       // [Bh|Bh]
}

// =============================================================================
// fp16 tensor-core GEMM via mma.sync. C[M,N] = A[M,K2] * Bt[N,K2]^T (+bias).
// CTA 128x128, 4 warps (2x2) of m64 x n64, K-chunk 64, 3-stage cp.async,
// register-fragment double buffering. B uses PLAIN ldmatrix (N-major, K contig).
// =============================================================================
#define GSTAGES   3
#define GSTAGE_B  32768                       // A 16KB + B 16KB
#define GEMM_SMEM (GSTAGES * GSTAGE_B)        // 96 KB

__device__ __forceinline__ void mma_f16(float* d, const uint32_t* a, const uint32_t* b)
{
    asm volatile(
        "mma.sync.aligned.m16n8k16.row.col.f32.f16.f16.f32 "
        "{%0,%1,%2,%3}, {%4,%5,%6,%7}, {%8,%9}, {%0,%1,%2,%3};"
        : "+f"(d[0]), "+f"(d[1]), "+f"(d[2]), "+f"(d[3])
        : "r"(a[0]), "r"(a[1]), "r"(a[2]), "r"(a[3]), "r"(b[0]), "r"(b[1]));
}

__device__ __forceinline__ void ldsm_x4(uint32_t* r, uint32_t a)
{
    asm volatile("ldmatrix.sync.aligned.m8n8.x4.shared.b16 {%0,%1,%2,%3}, [%4];"
        : "=r"(r[0]), "=r"(r[1]), "=r"(r[2]), "=r"(r[3]) : "r"(a));
}

__global__ void __launch_bounds__(128) gemm_mma_kernel(
    const __half* __restrict__ A,   // [M, K2] row-major
    const __half* __restrict__ Bt,  // [N, K2] row-major (N-major weights)
    float* __restrict__ C, const float* __restrict__ bias,
    int Nglob, int K2)
{
    extern __shared__ char smem[];
    const uint32_t sb = smem_u32(smem);
    const int tid  = threadIdx.x;
    const int warp = tid >> 5, lane = tid & 31;
    const int wm = warp & 1, wn = warp >> 1;
    const int m0 = blockIdx.y * 128, n0 = blockIdx.x * 128;
    const int nch = K2 >> 6;

    float acc[4][8][4];
#pragma unroll
    for (int i = 0; i < 4; ++i)
#pragma unroll
        for (int j = 0; j < 8; ++j)
#pragma unroll
            for (int t = 0; t < 4; ++t) acc[i][j][t] = 0.0f;

    const int a_row = wm * 64 + (lane & 15);
    const int a_k   = (lane >> 4);
    const int b_row = wn * 64 + ((lane & 16) >> 1) + (lane & 7);
    const int b_k   = ((lane >> 3) & 1);

    auto load_stage = [&](int s, int kc) {
        const uint32_t st = sb + s * GSTAGE_B;
#pragma unroll
        for (int it = 0; it < 8; ++it) {
            const int idx = it * 128 + tid;
            const int row = idx >> 3, c = idx & 7;
            cp_async16(st + row * 128 + ((c ^ (row & 7)) << 4),
                       A + (size_t)(m0 + row) * K2 + kc * 64 + c * 8);
        }
#pragma unroll
        for (int it = 0; it < 8; ++it) {
            const int idx = it * 128 + tid;
            const int row = idx >> 3, c = idx & 7;
            cp_async16(st + 16384 + row * 128 + ((c ^ (row & 7)) << 4),
                       Bt + (size_t)(n0 + row) * K2 + kc * 64 + c * 8);
        }
    };

    load_stage(0, 0); CP_COMMIT();
    load_stage(1, 1); CP_COMMIT();

    uint32_t af[2][4][4], bf[2][4][4];

    for (int i = 0; i < nch; ++i) {
        if (i + 2 < nch) load_stage((i + 2) % GSTAGES, i + 2);
        CP_COMMIT();
        CP_WAIT2();
        __syncthreads();

        const uint32_t stA = sb + (i % GSTAGES) * GSTAGE_B;
        const uint32_t stB = stA + 16384;

        auto load_frags = [&](int ks, int slot) {
#pragma unroll
            for (int mi = 0; mi < 4; ++mi) {
                const int row = a_row + mi * 16;
                const int kc  = 2 * ks + a_k;
                ldsm_x4(af[slot][mi], stA + row * 128 + ((kc ^ (row & 7)) << 4));
            }
#pragma unroll
            for (int nj = 0; nj < 4; ++nj) {
                const int row = b_row + nj * 16;
                const int kc  = 2 * ks + b_k;
                ldsm_x4(bf[slot][nj], stB + row * 128 + ((kc ^ (row & 7)) << 4));
            }
        };

        load_frags(0, 0);
#pragma unroll
        for (int ks = 0; ks < 4; ++ks) {
            const int cur = ks & 1;
            if (ks < 3) load_frags(ks + 1, cur ^ 1);
#pragma unroll
            for (int mi = 0; mi < 4; ++mi)
#pragma unroll
                for (int nj = 0; nj < 8; ++nj)
                    mma_f16(acc[mi][nj], af[cur][mi], &bf[cur][nj >> 1][(nj & 1) * 2]);
        }
        __syncthreads();
    }

    // epilogue
    const int g = lane >> 2, tg = lane & 3;
#pragma unroll
    for (int mi = 0; mi < 4; ++mi) {
        const int r0 = m0 + wm * 64 + mi * 16 + g;
#pragma unroll
        for (int nj = 0; nj < 8; ++nj) {
            const int col = n0 + wn * 64 + nj * 8 + tg * 2;
            float b0 = 0.0f, b1 = 0.0f;
            if (bias) { b0 = bias[col]; b1 = bias[col + 1]; }
            float2 o0 = make_float2(acc[mi][nj][0] + b0, acc[mi][nj][1] + b1);
            float2 o1 = make_float2(acc[mi][nj][2] + b0, acc[mi][nj][3] + b1);
            *(float2*)&C[(size_t)r0 * Nglob + col]       = o0;
            *(float2*)&C[(size_t)(r0 + 8) * Nglob + col] = o1;
        }
    }
}

// =============================================================================
// Attention: one block per point (8 warps = 8 heads); reads fused QKV,
// writes fp16 split activation [Ah|Al] (feeds the out-proj GEMM).
// =============================================================================
__global__ void __launch_bounds__(256) attn_kernel()
{
    const int point = blockIdx.x;
    const int warp  = threadIdx.x >> 5;
    const int lane  = threadIdx.x & 31;
    const int b     = point >> 13;
    const int baseb = b * NN;

    const int* idxp = g_IDX + (size_t)point * 8;
    const float2 qh = *(const float2*)&g_QKV[(size_t)point * NQKV + warp * DHD + lane * 2];

    float dots[8];
    int   nbs[8];
#pragma unroll
    for (int k = 0; k < 8; ++k) {
        const int nb = idxp[k];
        nbs[k] = nb;
        const float2 kk = *(const float2*)&g_QKV[(size_t)(baseb + nb) * NQKV + INNER + warp * DHD + lane * 2];
        float d = qh.x * kk.x + qh.y * kk.y;
#pragma unroll
        for (int o = 16; o; o >>= 1) d += __shfl_xor_sync(0xffffffffu, d, o);
        dots[k] = d * 0.125f;
    }

    float m = dots[0];
#pragma unroll
    for (int k = 1; k < 8; ++k) m = fmaxf(m, dots[k]);
    float e[8], s = 0.0f;
#pragma unroll
    for (int k = 0; k < 8; ++k) { e[k] = expf(dots[k] - m); s += e[k]; }
    const float inv = 1.0f / s;

    float2 acc = make_float2(0.0f, 0.0f);
#pragma unroll
    for (int k = 0; k < 8; ++k) {
        const float2 vv = *(const float2*)&g_QKV[(size_t)(baseb + nbs[k]) * NQKV + 2 * INNER + warp * DHD + lane * 2];
        const float a = e[k] * inv;
        acc.x = fmaf(a, vv.x, acc.x);
        acc.y = fmaf(a, vv.y, acc.y);
    }

    __half hx, lx, hy, ly;
    split_f16(acc.x, hx, lx);
    split_f16(acc.y, hy, ly);
    __half2 hp; hp.x = hx; hp.y = hy;
    __half2 lp; lp.x = lx; lp.y = ly;
    __half* r = g_AT2 + (size_t)point * K2_OUT + warp * DHD + lane * 2;
    *(__half2*)(r)         = hp;   // Ah
    *(__half2*)(r + INNER) = lp;   // Al
}

// =============================================================================
extern "C" void kernel_launch(void* const* d_in, const int* in_sizes, int n_in,
                              void* d_out, int out_size)
{
    const float* x    = (const float*)d_in[0];
    const float* pos  = (const float*)d_in[1];
    const float* Wq   = (const float*)d_in[2];
    const float* Wkv  = (const float*)d_in[3];
    const float* Wout = (const float*)d_in[4];
    const float* bout = (const float*)d_in[5];
    float* out = (float*)d_out;

    cudaFuncSetAttribute(gemm_mma_kernel,
                         cudaFuncAttributeMaxDynamicSharedMemorySize, GEMM_SMEM);

    __half *pX2, *pWT, *pWTO, *pAT2;
    float *pQKV;
    cudaGetSymbolAddress((void**)&pX2,  g_X2);
    cudaGetSymbolAddress((void**)&pWT,  g_WT);
    cudaGetSymbolAddress((void**)&pWTO, g_WTO);
    cudaGetSymbolAddress((void**)&pQKV, g_QKV);
    cudaGetSymbolAddress((void**)&pAT2, g_AT2);

    // 1) KNN + conversions
    knn_kernel<<<MTOT / 8, 256>>>(pos);
    conv_x_kernel<<<MTOT * DD / 256, 256>>>(x);
    conv_wqkv_kernel<<<NQKV * DD / 256, 256>>>(Wq, Wkv);
    conv_wout_kernel<<<DD * INNER / 256, 256>>>(Wout);

    // 2) fused QKV = x @ [Wq|Wkv]  (tensor cores, 2-term fp16 as K'=512)
    gemm_mma_kernel<<<dim3(NQKV / 128, MTOT / 128), 128, GEMM_SMEM>>>(
        pX2, pWT, pQKV, nullptr, NQKV, K2_QKV);

    // 3) neighbor attention (writes fp16 split activation)
    attn_kernel<<<MTOT, 256>>>();

    // 4) out = ATT @ Wout + bout   (tensor cores, 2-term fp16 as K'=1024)
    gemm_mma_kernel<<<dim3(DD / 128, MTOT / 128), 128, GEMM_SMEM>>>(
        pAT2, pWTO, out, bout, DD, K2_OUT);
}